// round 1
// baseline (speedup 1.0000x reference)
#include <cuda_runtime.h>
#include <cuda_bf16.h>

#define NUM_T 200
#define NBINS (NUM_T + 1)   // count in [0, 200]

// Scratch: positive-label and negative-label histograms (zeroed each launch).
__device__ int g_hist[2 * NBINS];

__global__ void zero_hist_kernel() {
    int i = threadIdx.x;
    if (i < 2 * NBINS) g_hist[i] = 0;
}

__global__ void hist_kernel(const float* __restrict__ pred,
                            const int* __restrict__ lab,
                            const float* __restrict__ thr,
                            int n) {
    __shared__ float s_thr[NUM_T];
    __shared__ int s_hist[2 * NBINS];

    for (int i = threadIdx.x; i < NUM_T; i += blockDim.x) s_thr[i] = thr[i];
    for (int i = threadIdx.x; i < 2 * NBINS; i += blockDim.x) s_hist[i] = 0;
    __syncthreads();

    const int tid = blockIdx.x * blockDim.x + threadIdx.x;
    const int stride = gridDim.x * blockDim.x;
    const int n4 = n >> 2;

    const float4* p4 = (const float4*)pred;
    const int4*   l4 = (const int4*)lab;

    for (int i = tid; i < n4; i += stride) {
        float4 p = p4[i];
        int4   l = l4[i];
        float pv[4] = {p.x, p.y, p.z, p.w};
        int   lv[4] = {l.x, l.y, l.z, l.w};
        #pragma unroll
        for (int c = 0; c < 4; c++) {
            float v = pv[c];
            // count = #{t : thr[t] < v}  == lower_bound index of v
            int lo = 0, hi = NUM_T;
            #pragma unroll
            for (int it = 0; it < 8; it++) {   // 2^8 = 256 >= 200
                int mid = (lo + hi) >> 1;
                if (lo < hi) {
                    if (s_thr[mid] < v) lo = mid + 1; else hi = mid;
                }
            }
            int base = (lv[c] != 0) ? 0 : NBINS;
            atomicAdd(&s_hist[base + lo], 1);
        }
    }
    // tail (n not multiple of 4) — handled by block 0 thread range
    if (blockIdx.x == 0) {
        for (int i = (n4 << 2) + threadIdx.x; i < n; i += blockDim.x) {
            float v = pred[i];
            int lo = 0, hi = NUM_T;
            while (lo < hi) {
                int mid = (lo + hi) >> 1;
                if (s_thr[mid] < v) lo = mid + 1; else hi = mid;
            }
            int base = (lab[i] != 0) ? 0 : NBINS;
            atomicAdd(&s_hist[base + lo], 1);
        }
    }
    __syncthreads();

    for (int i = threadIdx.x; i < 2 * NBINS; i += blockDim.x) {
        int v = s_hist[i];
        if (v) atomicAdd(&g_hist[i], v);
    }
}

__global__ void finalize_kernel(float* out) {
    // Single-thread epilogue: suffix sums over 201 bins + trapezoid.
    if (threadIdx.x != 0 || blockIdx.x != 0) return;

    const float EPS = 1e-06f;
    float tp[NUM_T], fp[NUM_T];

    // element is predicted-positive at threshold t iff count > t,
    // so tp[t] = sum_{k=t+1}^{200} posHist[k]
    float sp = 0.0f, sn = 0.0f;
    // bins above NUM_T-1: bin NUM_T contributes to all tp? No: count>t for t=NUM_T-1
    // needs count >= NUM_T, i.e. bin 200.
    // accumulate descending
    float accP = 0.0f, accN = 0.0f;
    // start with bin 200
    accP += (float)g_hist[NUM_T];
    accN += (float)g_hist[NBINS + NUM_T];
    for (int t = NUM_T - 1; t >= 0; t--) {
        tp[t] = accP;
        fp[t] = accN;
        accP += (float)g_hist[t];
        accN += (float)g_hist[NBINS + t];
    }
    float totP = accP;  // tp + fn at any threshold
    float totN = accN;  // fp + tn at any threshold
    (void)sp; (void)sn;

    float auc = 0.0f;
    for (int t = 0; t < NUM_T - 1; t++) {
        float y0 = (tp[t] + EPS) / (totP + EPS);
        float y1 = (tp[t + 1] + EPS) / (totP + EPS);
        float x0 = fp[t] / (totN + EPS);
        float x1 = fp[t + 1] / (totN + EPS);
        auc += (x0 - x1) * (y0 + y1) * 0.5f;
    }
    out[0] = auc;
}

extern "C" void kernel_launch(void* const* d_in, const int* in_sizes, int n_in,
                              void* d_out, int out_size) {
    const float* pred = (const float*)d_in[0];
    const int*   lab  = (const int*)d_in[1];
    const float* thr  = (const float*)d_in[2];
    float* out = (float*)d_out;
    int n = in_sizes[0];

    zero_hist_kernel<<<1, 512>>>();
    int threads = 256;
    int blocks = 592;  // 4 * 148 SMs
    hist_kernel<<<blocks, threads>>>(pred, lab, thr, n);
    finalize_kernel<<<1, 32>>>(out);
}